// round 1
// baseline (speedup 1.0000x reference)
#include <cuda_runtime.h>
#include <cuda_bf16.h>
#include <math.h>

// GCN: 3 layers, N=50000 nodes, E=800000 edges, dims 128->64->64->32.
// out[d] = dis[d] * (hs[d] + sum_{e: dst=d} hs[src_e]) + b ; hs = (h@W)*dis
// dis[i] = rsqrt(deg[i]) with deg = (#edges with dst=i) + 1 (self loop).

#define MAX_N 50000
#define MAX_D 64

__device__ float g_hs [MAX_N * MAX_D];
__device__ float g_agg[MAX_N * MAX_D];
__device__ float g_hA [MAX_N * MAX_D];
__device__ float g_hB [MAX_N * MAX_D];
__device__ float g_dis[MAX_N];
__device__ int   g_deg[MAX_N];

// ---------------------------------------------------------------------------
// degree / normalization
// ---------------------------------------------------------------------------
__global__ void deg_init_kernel(int* deg, int n) {
    int i = blockIdx.x * blockDim.x + threadIdx.x;
    if (i < n) deg[i] = 1;  // self loop
}

__global__ void deg_count_kernel(const int* __restrict__ dst, int* deg, int e) {
    int i = blockIdx.x * blockDim.x + threadIdx.x;
    if (i < e) atomicAdd(&deg[dst[i]], 1);
}

__global__ void dis_kernel(const int* __restrict__ deg, float* dis, int n) {
    int i = blockIdx.x * blockDim.x + threadIdx.x;
    if (i < n) dis[i] = rsqrtf((float)deg[i]);
}

// ---------------------------------------------------------------------------
// GEMM + pre-scale:  hs[row,:] = (in[row,:] @ W) * dis[row];  agg = hs (self term)
// One thread per row, OUT accumulators in registers, W broadcast from shared.
// ---------------------------------------------------------------------------
template <int IN, int OUT>
__global__ void gemm_scale_kernel(const float* __restrict__ in,
                                  const float* __restrict__ W,
                                  const float* __restrict__ dis,
                                  float* __restrict__ hs,
                                  float* __restrict__ agg,
                                  int n) {
    __shared__ float sW[IN * OUT];
    // cooperative load of W (float4)
    const int nt = blockDim.x;
    for (int i = threadIdx.x; i < IN * OUT / 4; i += nt)
        reinterpret_cast<float4*>(sW)[i] = reinterpret_cast<const float4*>(W)[i];
    __syncthreads();

    int row = blockIdx.x * blockDim.x + threadIdx.x;
    if (row >= n) return;

    float acc[OUT];
#pragma unroll
    for (int c = 0; c < OUT; c++) acc[c] = 0.0f;

    const float* xrow = in + (size_t)row * IN;
    for (int k0 = 0; k0 < IN; k0 += 4) {
        float4 xv = *reinterpret_cast<const float4*>(xrow + k0);
        float xs[4] = {xv.x, xv.y, xv.z, xv.w};
#pragma unroll
        for (int kk = 0; kk < 4; kk++) {
            const float* wr = sW + (k0 + kk) * OUT;
#pragma unroll
            for (int c = 0; c < OUT; c += 4) {
                float4 w = *reinterpret_cast<const float4*>(wr + c);
                acc[c + 0] += xs[kk] * w.x;
                acc[c + 1] += xs[kk] * w.y;
                acc[c + 2] += xs[kk] * w.z;
                acc[c + 3] += xs[kk] * w.w;
            }
        }
    }

    float d = dis[row];
    float4* hp = reinterpret_cast<float4*>(hs  + (size_t)row * OUT);
    float4* ap = reinterpret_cast<float4*>(agg + (size_t)row * OUT);
#pragma unroll
    for (int c = 0; c < OUT; c += 4) {
        float4 v;
        v.x = acc[c + 0] * d;
        v.y = acc[c + 1] * d;
        v.z = acc[c + 2] * d;
        v.w = acc[c + 3] * d;
        hp[c / 4] = v;
        ap[c / 4] = v;
    }
}

// ---------------------------------------------------------------------------
// Edge scatter: agg[dst,:] += hs[src,:] via vector float reduction (REDG)
// 16 (or 8) consecutive threads handle one edge -> coalesced float4 gather.
// ---------------------------------------------------------------------------
template <int OUT>
__global__ void scatter_kernel(const int* __restrict__ src,
                               const int* __restrict__ dst,
                               const float* __restrict__ hs,
                               float* __restrict__ agg,
                               int e) {
    const int C = OUT / 4;  // float4 chunks per edge
    long long t = (long long)blockIdx.x * blockDim.x + threadIdx.x;
    int ei = (int)(t / C);
    int c  = (int)(t % C);
    if (ei >= e) return;
    int s = src[ei];
    int d = dst[ei];
    float4 v = *reinterpret_cast<const float4*>(hs + (size_t)s * OUT + c * 4);
    float* p = agg + (size_t)d * OUT + c * 4;
    asm volatile("red.global.add.v4.f32 [%0], {%1, %2, %3, %4};"
                 :: "l"(p), "f"(v.x), "f"(v.y), "f"(v.z), "f"(v.w)
                 : "memory");
}

// ---------------------------------------------------------------------------
// Finalize: out[i,c] = [relu]( agg[i,c] * dis[i] + b[c] )
// ---------------------------------------------------------------------------
template <int OUT, bool RELU>
__global__ void finalize_kernel(const float* __restrict__ agg,
                                const float* __restrict__ dis,
                                const float* __restrict__ b,
                                float* __restrict__ out,
                                int n) {
    const int C = OUT / 4;
    int t = blockIdx.x * blockDim.x + threadIdx.x;
    int row = t / C;
    int c4  = t % C;
    if (row >= n) return;
    float d = dis[row];
    float4 v = *reinterpret_cast<const float4*>(agg + (size_t)row * OUT + c4 * 4);
    float4 bb = *reinterpret_cast<const float4*>(b + c4 * 4);
    float4 r;
    r.x = v.x * d + bb.x;
    r.y = v.y * d + bb.y;
    r.z = v.z * d + bb.z;
    r.w = v.w * d + bb.w;
    if (RELU) {
        r.x = fmaxf(r.x, 0.0f);
        r.y = fmaxf(r.y, 0.0f);
        r.z = fmaxf(r.z, 0.0f);
        r.w = fmaxf(r.w, 0.0f);
    }
    *reinterpret_cast<float4*>(out + (size_t)row * OUT + c4 * 4) = r;
}

// ---------------------------------------------------------------------------
// launch
// ---------------------------------------------------------------------------
extern "C" void kernel_launch(void* const* d_in, const int* in_sizes, int n_in,
                              void* d_out, int out_size) {
    const float* x    = (const float*)d_in[0];
    const int*   eidx = (const int*)  d_in[1];
    const float* W1   = (const float*)d_in[2];
    const float* b1   = (const float*)d_in[3];
    const float* W2   = (const float*)d_in[4];
    const float* b2   = (const float*)d_in[5];
    const float* W3   = (const float*)d_in[6];
    const float* b3   = (const float*)d_in[7];

    const int N = in_sizes[0] / 128;
    const int E = in_sizes[1] / 2;
    const int* esrc = eidx;
    const int* edst = eidx + E;

    float *hs, *agg, *hA, *hB, *dis;
    int* deg;
    cudaGetSymbolAddress((void**)&hs,  g_hs);
    cudaGetSymbolAddress((void**)&agg, g_agg);
    cudaGetSymbolAddress((void**)&hA,  g_hA);
    cudaGetSymbolAddress((void**)&hB,  g_hB);
    cudaGetSymbolAddress((void**)&dis, g_dis);
    cudaGetSymbolAddress((void**)&deg, g_deg);

    float* out = (float*)d_out;

    const int T = 256;

    // --- normalization ---
    deg_init_kernel<<<(N + T - 1) / T, T>>>(deg, N);
    deg_count_kernel<<<(E + T - 1) / T, T>>>(edst, deg, E);
    dis_kernel<<<(N + T - 1) / T, T>>>(deg, dis, N);

    // --- layer 1: 128 -> 64, relu ---
    gemm_scale_kernel<128, 64><<<(N + 127) / 128, 128>>>(x, W1, dis, hs, agg, N);
    {
        long long total = (long long)E * 16;
        scatter_kernel<64><<<(unsigned)((total + T - 1) / T), T>>>(esrc, edst, hs, agg, E);
    }
    finalize_kernel<64, true><<<(N * 16 + T - 1) / T, T>>>(agg, dis, b1, hA, N);

    // --- layer 2: 64 -> 64, relu ---
    gemm_scale_kernel<64, 64><<<(N + 127) / 128, 128>>>(hA, W2, dis, hs, agg, N);
    {
        long long total = (long long)E * 16;
        scatter_kernel<64><<<(unsigned)((total + T - 1) / T), T>>>(esrc, edst, hs, agg, E);
    }
    finalize_kernel<64, true><<<(N * 16 + T - 1) / T, T>>>(agg, dis, b2, hB, N);

    // --- layer 3: 64 -> 32, no relu, straight to d_out ---
    gemm_scale_kernel<64, 32><<<(N + 127) / 128, 128>>>(hB, W3, dis, hs, agg, N);
    {
        long long total = (long long)E * 8;
        scatter_kernel<32><<<(unsigned)((total + T - 1) / T), T>>>(esrc, edst, hs, agg, E);
    }
    finalize_kernel<32, false><<<(N * 8 + T - 1) / T, T>>>(agg, dis, b3, out, N);
}

// round 2
// speedup vs baseline: 1.4321x; 1.4321x over previous
#include <cuda_runtime.h>
#include <cuda_bf16.h>
#include <math.h>

// 3-layer GCN, N=50000, E=800000, dims 128->64->64->32.
// hs = (h@W)*dis ; out[d] = dis[d]*(hs[d] + sum_{src->d} hs[src]) + b
// Aggregation via CSR-by-dst gather (built once per call), no atomics in hot path.

#define NMAX 50000
#define EMAX 800000

__device__ float g_hs [NMAX * 64];
__device__ float g_hA [NMAX * 64];
__device__ float g_hB [NMAX * 64];
__device__ float g_dis[NMAX];
__device__ int   g_deg[NMAX];
__device__ int   g_scan[NMAX];
__device__ int   g_bsum[64];
__device__ int   g_rowptr[NMAX + 1];
__device__ int   g_cursor[NMAX];
__device__ int   g_col[EMAX];

// ---------------------------------------------------------------------------
// packed f32x2 helpers (sm_103a)
// ---------------------------------------------------------------------------
__device__ __forceinline__ unsigned long long pack2(float a, float b) {
    unsigned long long r;
    asm("mov.b64 %0, {%1, %2};" : "=l"(r) : "f"(a), "f"(b));
    return r;
}
__device__ __forceinline__ unsigned long long ffma2(unsigned long long a,
                                                    unsigned long long b,
                                                    unsigned long long c) {
    unsigned long long d;
    asm("fma.rn.f32x2 %0, %1, %2, %3;" : "=l"(d) : "l"(a), "l"(b), "l"(c));
    return d;
}
__device__ __forceinline__ unsigned long long fmul2(unsigned long long a,
                                                    unsigned long long b) {
    unsigned long long d;
    asm("mul.rn.f32x2 %0, %1, %2;" : "=l"(d) : "l"(a), "l"(b));
    return d;
}

// ---------------------------------------------------------------------------
// CSR build: degree -> scan -> fixup -> fill
// ---------------------------------------------------------------------------
__global__ void deg_zero_kernel(int* deg, int n) {
    int i = blockIdx.x * blockDim.x + threadIdx.x;
    if (i < n) deg[i] = 0;
}

__global__ void deg_count_kernel(const int* __restrict__ dst, int* deg, int e) {
    int i = blockIdx.x * blockDim.x + threadIdx.x;
    if (i < e) atomicAdd(&deg[dst[i]], 1);
}

__global__ void scan1_kernel(const int* __restrict__ deg, int* scanout,
                             int* bsum, int n) {
    __shared__ int s[1024];
    int i = blockIdx.x * 1024 + threadIdx.x;
    int v = (i < n) ? deg[i] : 0;
    s[threadIdx.x] = v;
    __syncthreads();
#pragma unroll
    for (int off = 1; off < 1024; off <<= 1) {
        int add = (threadIdx.x >= off) ? s[threadIdx.x - off] : 0;
        __syncthreads();
        s[threadIdx.x] += add;
        __syncthreads();
    }
    if (i < n) scanout[i] = s[threadIdx.x];
    if (threadIdx.x == 1023) bsum[blockIdx.x] = s[1023];
}

__global__ void scan2_kernel(int* bsum, int nb) {
    __shared__ int s[64];
    if (threadIdx.x < nb) s[threadIdx.x] = bsum[threadIdx.x];
    __syncthreads();
    if (threadIdx.x == 0) {
        int run = 0;
        for (int j = 0; j < nb; j++) { int t = s[j]; s[j] = run; run += t; }
    }
    __syncthreads();
    if (threadIdx.x < nb) bsum[threadIdx.x] = s[threadIdx.x];
}

__global__ void fixup_kernel(const int* __restrict__ scanin,
                             const int* __restrict__ deg,
                             const int* __restrict__ bsum,
                             int* rowptr, int* cursor, float* dis,
                             int n, int e) {
    int i = blockIdx.x * blockDim.x + threadIdx.x;
    if (i < n) {
        int rp = scanin[i] - deg[i] + bsum[i >> 10];  // exclusive prefix
        rowptr[i] = rp;
        cursor[i] = rp;
        dis[i] = rsqrtf((float)(deg[i] + 1));         // +1 self loop
    }
    if (i == 0) rowptr[n] = e;
}

__global__ void fill_kernel(const int* __restrict__ src,
                            const int* __restrict__ dst,
                            int* cursor, int* col, int e) {
    int i = blockIdx.x * blockDim.x + threadIdx.x;
    if (i < e) {
        int p = atomicAdd(&cursor[dst[i]], 1);
        col[p] = src[i];
    }
}

// ---------------------------------------------------------------------------
// GEMM + pre-scale: hs[row,:] = (in[row,:] @ W) * dis[row]
// Thread-per-row, W broadcast from shared, packed f32x2 FMAs (2 cols/instr).
// ---------------------------------------------------------------------------
template <int IN, int OUT>
__global__ void gemm_kernel(const float* __restrict__ in,
                            const float* __restrict__ W,
                            const float* __restrict__ dis,
                            float* __restrict__ hs, int n) {
    __shared__ __align__(16) float sW[IN * OUT];
    for (int i = threadIdx.x; i < IN * OUT / 4; i += blockDim.x)
        reinterpret_cast<float4*>(sW)[i] = reinterpret_cast<const float4*>(W)[i];
    __syncthreads();

    int row = blockIdx.x * blockDim.x + threadIdx.x;
    if (row >= n) return;

    unsigned long long acc[OUT / 2];
#pragma unroll
    for (int c = 0; c < OUT / 2; c++) acc[c] = 0ULL;

    const float* xr = in + (size_t)row * IN;
    for (int k0 = 0; k0 < IN; k0 += 4) {
        float4 xv = *reinterpret_cast<const float4*>(xr + k0);
        float xs[4] = {xv.x, xv.y, xv.z, xv.w};
#pragma unroll
        for (int kk = 0; kk < 4; kk++) {
            unsigned long long xx = pack2(xs[kk], xs[kk]);
            const ulonglong2* wr =
                reinterpret_cast<const ulonglong2*>(sW + (k0 + kk) * OUT);
#pragma unroll
            for (int c4 = 0; c4 < OUT / 4; c4++) {
                ulonglong2 w = wr[c4];
                acc[c4 * 2 + 0] = ffma2(xx, w.x, acc[c4 * 2 + 0]);
                acc[c4 * 2 + 1] = ffma2(xx, w.y, acc[c4 * 2 + 1]);
            }
        }
    }

    float d = dis[row];
    unsigned long long dd = pack2(d, d);
    ulonglong2* hp = reinterpret_cast<ulonglong2*>(hs + (size_t)row * OUT);
#pragma unroll
    for (int c4 = 0; c4 < OUT / 4; c4++) {
        ulonglong2 r;
        r.x = fmul2(acc[c4 * 2 + 0], dd);
        r.y = fmul2(acc[c4 * 2 + 1], dd);
        hp[c4] = r;
    }
}

// ---------------------------------------------------------------------------
// Gather + finalize: out[d,:] = [relu]( dis[d]*(hs[d,:] + sum_in hs[src,:]) + b )
// OUT/4 lanes per node; each lane owns one float4 chunk.
// ---------------------------------------------------------------------------
template <int OUT, bool RELU>
__global__ void gather_kernel(const int* __restrict__ rowptr,
                              const int* __restrict__ col,
                              const float* __restrict__ hs,
                              const float* __restrict__ dis,
                              const float* __restrict__ bias,
                              float* __restrict__ out, int n) {
    const int G = OUT / 4;
    int t = blockIdx.x * blockDim.x + threadIdx.x;
    int gid = t / G;
    int lane = t % G;
    if (gid >= n) return;

    const float4* hs4 = reinterpret_cast<const float4*>(hs);
    int beg = rowptr[gid];
    int end = rowptr[gid + 1];

    float4 acc = hs4[(size_t)gid * G + lane];  // self term
#pragma unroll 4
    for (int e = beg; e < end; e++) {
        int s = __ldg(&col[e]);
        float4 v = hs4[(size_t)s * G + lane];
        acc.x += v.x; acc.y += v.y; acc.z += v.z; acc.w += v.w;
    }

    float d = dis[gid];
    float4 b4 = reinterpret_cast<const float4*>(bias)[lane];
    float4 r;
    r.x = acc.x * d + b4.x;
    r.y = acc.y * d + b4.y;
    r.z = acc.z * d + b4.z;
    r.w = acc.w * d + b4.w;
    if (RELU) {
        r.x = fmaxf(r.x, 0.0f);
        r.y = fmaxf(r.y, 0.0f);
        r.z = fmaxf(r.z, 0.0f);
        r.w = fmaxf(r.w, 0.0f);
    }
    reinterpret_cast<float4*>(out)[(size_t)gid * G + lane] = r;
}

// ---------------------------------------------------------------------------
// launch
// ---------------------------------------------------------------------------
extern "C" void kernel_launch(void* const* d_in, const int* in_sizes, int n_in,
                              void* d_out, int out_size) {
    const float* x    = (const float*)d_in[0];
    const int*   eidx = (const int*)  d_in[1];
    const float* W1   = (const float*)d_in[2];
    const float* b1   = (const float*)d_in[3];
    const float* W2   = (const float*)d_in[4];
    const float* b2   = (const float*)d_in[5];
    const float* W3   = (const float*)d_in[6];
    const float* b3   = (const float*)d_in[7];

    const int N = in_sizes[0] / 128;
    const int E = in_sizes[1] / 2;
    const int* esrc = eidx;
    const int* edst = eidx + E;

    float *hs, *hA, *hB, *dis;
    int *deg, *scn, *bsum, *rowptr, *cursor, *col;
    cudaGetSymbolAddress((void**)&hs,     g_hs);
    cudaGetSymbolAddress((void**)&hA,     g_hA);
    cudaGetSymbolAddress((void**)&hB,     g_hB);
    cudaGetSymbolAddress((void**)&dis,    g_dis);
    cudaGetSymbolAddress((void**)&deg,    g_deg);
    cudaGetSymbolAddress((void**)&scn,    g_scan);
    cudaGetSymbolAddress((void**)&bsum,   g_bsum);
    cudaGetSymbolAddress((void**)&rowptr, g_rowptr);
    cudaGetSymbolAddress((void**)&cursor, g_cursor);
    cudaGetSymbolAddress((void**)&col,    g_col);

    float* out = (float*)d_out;

    const int T = 256;
    const int NB = (N + 1023) / 1024;

    // --- CSR build + normalization ---
    deg_zero_kernel <<<(N + T - 1) / T, T>>>(deg, N);
    deg_count_kernel<<<(E + T - 1) / T, T>>>(edst, deg, E);
    scan1_kernel    <<<NB, 1024>>>(deg, scn, bsum, N);
    scan2_kernel    <<<1, 64>>>(bsum, NB);
    fixup_kernel    <<<(N + T - 1) / T, T>>>(scn, deg, bsum, rowptr, cursor, dis, N, E);
    fill_kernel     <<<(E + T - 1) / T, T>>>(esrc, edst, cursor, col, E);

    // --- layer 1: 128 -> 64, relu ---
    gemm_kernel<128, 64><<<(N + 127) / 128, 128>>>(x, W1, dis, hs, N);
    gather_kernel<64, true><<<(N * 16 + T - 1) / T, T>>>(rowptr, col, hs, dis, b1, hA, N);

    // --- layer 2: 64 -> 64, relu ---
    gemm_kernel<64, 64><<<(N + 127) / 128, 128>>>(hA, W2, dis, hs, N);
    gather_kernel<64, true><<<(N * 16 + T - 1) / T, T>>>(rowptr, col, hs, dis, b2, hB, N);

    // --- layer 3: 64 -> 32, no relu ---
    gemm_kernel<64, 32><<<(N + 127) / 128, 128>>>(hB, W3, dis, hs, N);
    gather_kernel<32, false><<<(N * 8 + T - 1) / T, T>>>(rowptr, col, hs, dis, b3, out, N);
}